// round 7
// baseline (speedup 1.0000x reference)
#include <cuda_runtime.h>
#include <stdint.h>

#define N_MAX 100000
#define E_MAX 800000

typedef unsigned long long ull;

// Scratch (device globals; no allocation allowed in kernel_launch)
__device__ float g_bufA[(size_t)N_MAX * 64];
__device__ float g_bufB[(size_t)N_MAX * 64];
__device__ float g_h3[(size_t)N_MAX * 7];
__device__ float g_dinv[N_MAX];
__device__ int   g_deg[N_MAX];
__device__ int   g_ptr[N_MAX];
__device__ int   g_fill[N_MAX];
__device__ int   g_csr[E_MAX];
__device__ int   g_blockSums[512];

// ---------------------------------------------------------------------------
// degree
// ---------------------------------------------------------------------------
__global__ void k_zero_deg(int n) {
    int i = blockIdx.x * blockDim.x + threadIdx.x;
    if (i < n) g_deg[i] = 0;
}

__global__ void k_count_deg(const int* __restrict__ ei, int nE) {
    int e = blockIdx.x * blockDim.x + threadIdx.x;
    if (e < nE) atomicAdd(&g_deg[ei[nE + e]], 1);
}

// ---------------------------------------------------------------------------
// CSR build: exclusive prefix sum over deg (3 kernels), then atomic fill.
// dinv computed in scanC (fused).
// ---------------------------------------------------------------------------
__global__ void k_scanA(int n) {
    __shared__ int sh[256];
    int i = blockIdx.x * 256 + threadIdx.x;
    int t = threadIdx.x;
    sh[t] = (i < n) ? g_deg[i] : 0;
    __syncthreads();
    for (int s = 128; s > 0; s >>= 1) {
        if (t < s) sh[t] += sh[t + s];
        __syncthreads();
    }
    if (t == 0) g_blockSums[blockIdx.x] = sh[0];
}

__global__ void k_scanB(int nb) {
    __shared__ int sh[512];
    int t = threadIdx.x;
    int v = (t < nb) ? g_blockSums[t] : 0;
    sh[t] = v;
    __syncthreads();
    for (int off = 1; off < 512; off <<= 1) {
        int x = (t >= off) ? sh[t - off] : 0;
        __syncthreads();
        sh[t] += x;
        __syncthreads();
    }
    if (t < nb) g_blockSums[t] = sh[t] - v;   // exclusive
}

__global__ void k_scanC(int n) {
    __shared__ int sh[256];
    int i = blockIdx.x * 256 + threadIdx.x;
    int t = threadIdx.x;
    int v = (i < n) ? g_deg[i] : 0;
    sh[t] = v;
    __syncthreads();
    for (int off = 1; off < 256; off <<= 1) {
        int x = (t >= off) ? sh[t - off] : 0;
        __syncthreads();
        sh[t] += x;
        __syncthreads();
    }
    if (i < n) {
        int excl = sh[t] - v + g_blockSums[blockIdx.x];
        g_ptr[i]  = excl;
        g_fill[i] = excl;
        g_dinv[i] = rsqrtf((float)v + 1.0f);
    }
}

__global__ void k_fill(const int* __restrict__ ei, int nE) {
    int e = blockIdx.x * blockDim.x + threadIdx.x;
    if (e < nE) {
        int s = ei[e];
        int d = ei[nE + e];
        int pos = atomicAdd(&g_fill[d], 1);
        g_csr[pos] = s;
    }
}

// ---------------------------------------------------------------------------
// f32x2 helpers
// ---------------------------------------------------------------------------
__device__ __forceinline__ ull pack_dup(float v) {
    ull r;
    asm("mov.b64 %0, {%1, %1};" : "=l"(r) : "f"(v));
    return r;
}
__device__ __forceinline__ void ffma2(ull& acc, ull a, ull b) {
    asm("fma.rn.f32x2 %0, %1, %2, %0;" : "+l"(acc) : "l"(a), "l"(b));
}
__device__ __forceinline__ ull mul2(ull a, ull b) {
    ull r;
    asm("mul.rn.f32x2 %0, %1, %2;" : "=l"(r) : "l"(a), "l"(b));
    return r;
}
__device__ __forceinline__ void add2(ull& acc, ull v) {
    asm("add.rn.f32x2 %0, %0, %1;" : "+l"(acc) : "l"(v));
}

// ---------------------------------------------------------------------------
// GEMM (R4-proven shape): [n x K] @ [K x 64] -> hs_out = (RELU(in)@W)*dinv
// Block: 256 threads, tile 64 rows x 64 cols, thread tile 4x4, f32x2 FFMA2.
// ---------------------------------------------------------------------------
template <int K, bool RELU>
__global__ void __launch_bounds__(256) k_gemm64(
    const float* __restrict__ in, const float* __restrict__ W,
    float* __restrict__ hs_out, int n)
{
    constexpr int KC = 32;
    __shared__ float xs[KC][72];   // transposed [k][row]
    __shared__ float ws[KC][64];   // [k][col]

    int tid = threadIdx.x;
    int tx = tid & 15, ty = tid >> 4;
    int rowBase = blockIdx.x * 64;
    int r0 = ty * 4, c0 = tx * 4;

    ull acc2[4][2];
#pragma unroll
    for (int i = 0; i < 4; i++) { acc2[i][0] = 0ull; acc2[i][1] = 0ull; }

    int lr = tid >> 2;           // 0..63 (row)
    int lk = (tid & 3) * 8;      // 0,8,16,24 (k offset)

    for (int k0 = 0; k0 < K; k0 += KC) {
        // stage x tile (transposed)
        {
            int grow = rowBase + lr;
            float4 v0, v1;
            if (grow < n) {
                const float* p = in + (size_t)grow * K + k0 + lk;
                v0 = *(const float4*)p;
                v1 = *(const float4*)(p + 4);
            } else {
                v0 = make_float4(0.f, 0.f, 0.f, 0.f);
                v1 = v0;
            }
            if (RELU) {
                v0.x = fmaxf(v0.x, 0.f); v0.y = fmaxf(v0.y, 0.f);
                v0.z = fmaxf(v0.z, 0.f); v0.w = fmaxf(v0.w, 0.f);
                v1.x = fmaxf(v1.x, 0.f); v1.y = fmaxf(v1.y, 0.f);
                v1.z = fmaxf(v1.z, 0.f); v1.w = fmaxf(v1.w, 0.f);
            }
            xs[lk + 0][lr] = v0.x; xs[lk + 1][lr] = v0.y;
            xs[lk + 2][lr] = v0.z; xs[lk + 3][lr] = v0.w;
            xs[lk + 4][lr] = v1.x; xs[lk + 5][lr] = v1.y;
            xs[lk + 6][lr] = v1.z; xs[lk + 7][lr] = v1.w;
        }
        // stage W tile
        {
            int lkk = tid >> 3;            // 0..31
            int lc  = (tid & 7) * 8;       // 0..56
            const float* p = W + (size_t)(k0 + lkk) * 64 + lc;
            float4 w0 = *(const float4*)p;
            float4 w1 = *(const float4*)(p + 4);
            *(float4*)&ws[lkk][lc]     = w0;
            *(float4*)&ws[lkk][lc + 4] = w1;
        }
        __syncthreads();
#pragma unroll
        for (int kk = 0; kk < KC; kk++) {
            float4 xv = *(const float4*)&xs[kk][r0];
            const ull* wp = (const ull*)&ws[kk][c0];
            ull w0 = wp[0], w1 = wp[1];
            ull x0 = pack_dup(xv.x);
            ull x1 = pack_dup(xv.y);
            ull x2 = pack_dup(xv.z);
            ull x3 = pack_dup(xv.w);
            ffma2(acc2[0][0], x0, w0); ffma2(acc2[0][1], x0, w1);
            ffma2(acc2[1][0], x1, w0); ffma2(acc2[1][1], x1, w1);
            ffma2(acc2[2][0], x2, w0); ffma2(acc2[2][1], x2, w1);
            ffma2(acc2[3][0], x3, w0); ffma2(acc2[3][1], x3, w1);
        }
        __syncthreads();
    }

    // epilogue: hs = h * dinv[row]
#pragma unroll
    for (int i = 0; i < 4; i++) {
        int grow = rowBase + r0 + i;
        if (grow < n) {
            ull dd2 = pack_dup(g_dinv[grow]);
            longlong2 st;
            st.x = (long long)mul2(acc2[i][0], dd2);
            st.y = (long long)mul2(acc2[i][1], dd2);
            *(longlong2*)&hs_out[(size_t)grow * 64 + c0] = st;
        }
    }
}

// ---------------------------------------------------------------------------
// CSR pull aggregation (64-wide): one warp per dst node.
// out[d] = b + dinv[d] * ( hs[d] + sum_{s in N(d)} hs[s] )
// ---------------------------------------------------------------------------
__global__ void __launch_bounds__(256) k_agg64_csr(
    const float* __restrict__ hs, const float* __restrict__ b,
    float* __restrict__ out, int n)
{
    int warp = (blockIdx.x * 256 + threadIdx.x) >> 5;
    int lane = threadIdx.x & 31;
    if (warp >= n) return;
    int d = warp;

    float dd = g_dinv[d];
    int start = g_ptr[d];
    int deg   = g_deg[d];

    ull acc = *(const ull*)(hs + (size_t)d * 64 + lane * 2);

    for (int base = 0; base < deg; base += 32) {
        int cnt = min(32, deg - base);
        int s = 0;
        if (lane < cnt) s = g_csr[start + base + lane];
#pragma unroll 4
        for (int j = 0; j < cnt; j++) {
            int sj = __shfl_sync(0xffffffffu, s, j);
            ull v = *(const ull*)(hs + (size_t)sj * 64 + lane * 2);
            add2(acc, v);
        }
    }
    float2 av;
    av.x = __uint_as_float((unsigned)(acc & 0xffffffffull));
    av.y = __uint_as_float((unsigned)(acc >> 32));
    float2 bb = *(const float2*)(b + lane * 2);
    float2 o;
    o.x = fmaf(av.x, dd, bb.x);
    o.y = fmaf(av.y, dd, bb.y);
    *(float2*)(out + (size_t)d * 64 + lane * 2) = o;
}

// ---------------------------------------------------------------------------
// Layer 3 GEMM: h3s = (relu(in) @ W3) * dinv[row]   [n x 64] @ [64 x 7]
// ---------------------------------------------------------------------------
__global__ void __launch_bounds__(256) k_gemm7(
    const float* __restrict__ in, const float* __restrict__ W,
    float* __restrict__ hs_out, int n)
{
    __shared__ float wsh[64 * 7];
    int tid = threadIdx.x;
    for (int i = tid; i < 448; i += 256) wsh[i] = W[i];
    __syncthreads();

    int row = blockIdx.x * blockDim.x + tid;
    if (row >= n) return;

    float acc[7];
#pragma unroll
    for (int c = 0; c < 7; c++) acc[c] = 0.f;

    const float* p = in + (size_t)row * 64;
#pragma unroll
    for (int k = 0; k < 64; k += 4) {
        float4 v = *(const float4*)(p + k);
        v.x = fmaxf(v.x, 0.f); v.y = fmaxf(v.y, 0.f);
        v.z = fmaxf(v.z, 0.f); v.w = fmaxf(v.w, 0.f);
#pragma unroll
        for (int c = 0; c < 7; c++) {
            acc[c] = fmaf(v.x, wsh[(k + 0) * 7 + c], acc[c]);
            acc[c] = fmaf(v.y, wsh[(k + 1) * 7 + c], acc[c]);
            acc[c] = fmaf(v.z, wsh[(k + 2) * 7 + c], acc[c]);
            acc[c] = fmaf(v.w, wsh[(k + 3) * 7 + c], acc[c]);
        }
    }
    float di = g_dinv[row];
#pragma unroll
    for (int c = 0; c < 7; c++)
        hs_out[(size_t)row * 7 + c] = acc[c] * di;
}

// ---------------------------------------------------------------------------
// CSR pull aggregation (7-wide): one warp per dst node, lanes 0..6 hold cols.
// ---------------------------------------------------------------------------
__global__ void __launch_bounds__(256) k_agg7_csr(
    const float* __restrict__ hs, const float* __restrict__ b,
    float* __restrict__ out, int n)
{
    int warp = (blockIdx.x * 256 + threadIdx.x) >> 5;
    int lane = threadIdx.x & 31;
    if (warp >= n) return;
    int d = warp;

    float dd = g_dinv[d];
    int start = g_ptr[d];
    int deg   = g_deg[d];

    float acc = 0.f;
    if (lane < 7) acc = hs[(size_t)d * 7 + lane];

    for (int base = 0; base < deg; base += 32) {
        int cnt = min(32, deg - base);
        int s = 0;
        if (lane < cnt) s = g_csr[start + base + lane];
        for (int j = 0; j < cnt; j++) {
            int sj = __shfl_sync(0xffffffffu, s, j);
            if (lane < 7) acc += hs[(size_t)sj * 7 + lane];
        }
    }
    if (lane < 7)
        out[(size_t)d * 7 + lane] = fmaf(acc, dd, b[lane]);
}

// ---------------------------------------------------------------------------
// launch
// ---------------------------------------------------------------------------
extern "C" void kernel_launch(void* const* d_in, const int* in_sizes, int n_in,
                              void* d_out, int out_size)
{
    const float* x  = (const float*)d_in[0];
    const int*   ei = (const int*)d_in[1];
    const float* W1 = (const float*)d_in[2];
    const float* b1 = (const float*)d_in[3];
    const float* W2 = (const float*)d_in[4];
    const float* b2 = (const float*)d_in[5];
    const float* W3 = (const float*)d_in[6];
    const float* b3 = (const float*)d_in[7];

    int n  = in_sizes[0] / 128;
    int nE = in_sizes[1] / 2;
    float* out = (float*)d_out;

    float *bufA, *bufB, *h3;
    cudaGetSymbolAddress((void**)&bufA, g_bufA);
    cudaGetSymbolAddress((void**)&bufB, g_bufB);
    cudaGetSymbolAddress((void**)&h3,   g_h3);

    int nb_n = (n + 255) / 256;
    int nb_e = (nE + 255) / 256;
    int nb_g = (n + 63) / 64;                            // 64-row GEMM tiles
    int nb_w = (int)(((long long)n * 32 + 255) / 256);   // warp-per-node grids

    // degree + CSR + dinv (once, reused by all 3 layers)
    k_zero_deg<<<nb_n, 256>>>(n);
    k_count_deg<<<nb_e, 256>>>(ei, nE);
    k_scanA<<<nb_n, 256>>>(n);
    k_scanB<<<1, 512>>>(nb_n);
    k_scanC<<<nb_n, 256>>>(n);
    k_fill<<<nb_e, 256>>>(ei, nE);

    // layer 1: hs1 = (x@W1)*dinv -> bufA ; bufB = b1 + dinv*(hs1[d]+sum hs1[s])
    k_gemm64<128, false><<<nb_g, 256>>>(x, W1, bufA, n);
    k_agg64_csr<<<nb_w, 256>>>(bufA, b1, bufB, n);

    // layer 2
    k_gemm64<64, true><<<nb_g, 256>>>(bufB, W2, bufA, n);
    k_agg64_csr<<<nb_w, 256>>>(bufA, b2, bufB, n);

    // layer 3
    k_gemm7<<<nb_n, 256>>>(bufB, W3, h3, n);
    k_agg7_csr<<<nb_w, 256>>>(h3, b3, out, n);
}

// round 8
// speedup vs baseline: 1.4447x; 1.4447x over previous
#include <cuda_runtime.h>
#include <stdint.h>

#define N_MAX 100000
#define E_MAX 800000

// Scratch (device globals; no allocation allowed in kernel_launch)
__device__ float g_bufA[(size_t)N_MAX * 64];
__device__ float g_bufB[(size_t)N_MAX * 64];
__device__ float g_h3[(size_t)N_MAX * 7];
__device__ float g_dinv[N_MAX];
__device__ int   g_deg[N_MAX];
__device__ int   g_ptr[N_MAX];
__device__ int   g_fill[N_MAX];
__device__ int   g_csr[E_MAX];
__device__ int   g_blockSums[512];

// ---------------------------------------------------------------------------
// degree
// ---------------------------------------------------------------------------
__global__ void k_zero_deg(int n) {
    int i = blockIdx.x * blockDim.x + threadIdx.x;
    if (i < n) g_deg[i] = 0;
}

__global__ void k_count_deg(const int* __restrict__ ei, int nE) {
    int e = blockIdx.x * blockDim.x + threadIdx.x;
    if (e < nE) atomicAdd(&g_deg[ei[nE + e]], 1);
}

// ---------------------------------------------------------------------------
// CSR build: scanA computes per-block degree sums; scanC reduces its own
// block-sum prefix (no separate scanB launch), does the intra-block scan,
// writes ptr/fill, and computes dinv (no separate dinv launch).
// ---------------------------------------------------------------------------
__global__ void k_scanA(int n) {
    __shared__ int sh[256];
    int i = blockIdx.x * 256 + threadIdx.x;
    int t = threadIdx.x;
    sh[t] = (i < n) ? g_deg[i] : 0;
    __syncthreads();
    for (int s = 128; s > 0; s >>= 1) {
        if (t < s) sh[t] += sh[t + s];
        __syncthreads();
    }
    if (t == 0) g_blockSums[blockIdx.x] = sh[0];
}

__global__ void k_scanC(int n) {
    __shared__ int sh[256];
    __shared__ int blockOff;
    int i = blockIdx.x * 256 + threadIdx.x;
    int t = threadIdx.x;

    // phase 1: reduce blockSums[0 .. blockIdx.x-1]
    int partial = 0;
    for (int j = t; j < blockIdx.x; j += 256) partial += g_blockSums[j];
    sh[t] = partial;
    __syncthreads();
    for (int s = 128; s > 0; s >>= 1) {
        if (t < s) sh[t] += sh[t + s];
        __syncthreads();
    }
    if (t == 0) blockOff = sh[0];
    __syncthreads();

    // phase 2: intra-block exclusive scan of degrees
    int v = (i < n) ? g_deg[i] : 0;
    sh[t] = v;
    __syncthreads();
    for (int off = 1; off < 256; off <<= 1) {
        int x = (t >= off) ? sh[t - off] : 0;
        __syncthreads();
        sh[t] += x;
        __syncthreads();
    }
    if (i < n) {
        int excl = sh[t] - v + blockOff;
        g_ptr[i]  = excl;
        g_fill[i] = excl;
        g_dinv[i] = rsqrtf((float)v + 1.0f);
    }
}

__global__ void k_fill(const int* __restrict__ ei, int nE) {
    int e = blockIdx.x * blockDim.x + threadIdx.x;
    if (e < nE) {
        int s = ei[e];
        int d = ei[nE + e];
        int pos = atomicAdd(&g_fill[d], 1);
        g_csr[pos] = s;
    }
}

// ---------------------------------------------------------------------------
// f32x2 helpers
// ---------------------------------------------------------------------------
__device__ __forceinline__ unsigned long long pack_dup(float v) {
    unsigned long long r;
    asm("mov.b64 %0, {%1, %1};" : "=l"(r) : "f"(v));
    return r;
}
__device__ __forceinline__ void ffma2(unsigned long long& acc,
                                      unsigned long long a,
                                      unsigned long long b) {
    asm("fma.rn.f32x2 %0, %1, %2, %0;" : "+l"(acc) : "l"(a), "l"(b));
}

// ---------------------------------------------------------------------------
// GEMM (213us-proven): [n x K] @ [K x 64] -> h_out [n x 64]
// Optional ReLU applied to the INPUT (fuses previous layer's activation).
// Block: 256 threads, tile 64 rows x 64 cols, thread tile 4x4, f32x2 FFMA2.
// ---------------------------------------------------------------------------
template <int K, bool RELU>
__global__ void __launch_bounds__(256) k_gemm64(
    const float* __restrict__ in, const float* __restrict__ W,
    float* __restrict__ h_out, int n)
{
    constexpr int KC = 32;
    __shared__ float xs[KC][72];
    __shared__ float ws[KC][64];

    int tid = threadIdx.x;
    int tx = tid & 15, ty = tid >> 4;
    int rowBase = blockIdx.x * 64;
    int r0 = ty * 4, c0 = tx * 4;

    unsigned long long acc2[4][2];
#pragma unroll
    for (int i = 0; i < 4; i++) { acc2[i][0] = 0ull; acc2[i][1] = 0ull; }

    int lr = tid >> 2;
    int lk = (tid & 3) * 8;

    for (int k0 = 0; k0 < K; k0 += KC) {
        {
            int grow = rowBase + lr;
            float4 v0, v1;
            if (grow < n) {
                const float* p = in + (size_t)grow * K + k0 + lk;
                v0 = *(const float4*)p;
                v1 = *(const float4*)(p + 4);
            } else {
                v0 = make_float4(0.f, 0.f, 0.f, 0.f);
                v1 = v0;
            }
            if (RELU) {
                v0.x = fmaxf(v0.x, 0.f); v0.y = fmaxf(v0.y, 0.f);
                v0.z = fmaxf(v0.z, 0.f); v0.w = fmaxf(v0.w, 0.f);
                v1.x = fmaxf(v1.x, 0.f); v1.y = fmaxf(v1.y, 0.f);
                v1.z = fmaxf(v1.z, 0.f); v1.w = fmaxf(v1.w, 0.f);
            }
            xs[lk + 0][lr] = v0.x; xs[lk + 1][lr] = v0.y;
            xs[lk + 2][lr] = v0.z; xs[lk + 3][lr] = v0.w;
            xs[lk + 4][lr] = v1.x; xs[lk + 5][lr] = v1.y;
            xs[lk + 6][lr] = v1.z; xs[lk + 7][lr] = v1.w;
        }
        {
            int lkk = tid >> 3;
            int lc  = (tid & 7) * 8;
            const float* p = W + (size_t)(k0 + lkk) * 64 + lc;
            float4 w0 = *(const float4*)p;
            float4 w1 = *(const float4*)(p + 4);
            *(float4*)&ws[lkk][lc]     = w0;
            *(float4*)&ws[lkk][lc + 4] = w1;
        }
        __syncthreads();
#pragma unroll
        for (int kk = 0; kk < KC; kk++) {
            float4 xv = *(const float4*)&xs[kk][r0];
            const unsigned long long* wp =
                (const unsigned long long*)&ws[kk][c0];
            unsigned long long w0 = wp[0], w1 = wp[1];
            unsigned long long x0 = pack_dup(xv.x);
            unsigned long long x1 = pack_dup(xv.y);
            unsigned long long x2 = pack_dup(xv.z);
            unsigned long long x3 = pack_dup(xv.w);
            ffma2(acc2[0][0], x0, w0); ffma2(acc2[0][1], x0, w1);
            ffma2(acc2[1][0], x1, w0); ffma2(acc2[1][1], x1, w1);
            ffma2(acc2[2][0], x2, w0); ffma2(acc2[2][1], x2, w1);
            ffma2(acc2[3][0], x3, w0); ffma2(acc2[3][1], x3, w1);
        }
        __syncthreads();
    }

#pragma unroll
    for (int i = 0; i < 4; i++) {
        int grow = rowBase + r0 + i;
        if (grow < n) {
            float4 hv;
            hv.x = __uint_as_float((unsigned)(acc2[i][0] & 0xffffffffull));
            hv.y = __uint_as_float((unsigned)(acc2[i][0] >> 32));
            hv.z = __uint_as_float((unsigned)(acc2[i][1] & 0xffffffffull));
            hv.w = __uint_as_float((unsigned)(acc2[i][1] >> 32));
            *(float4*)&h_out[(size_t)grow * 64 + c0] = hv;
        }
    }
}

// ---------------------------------------------------------------------------
// CSR pull aggregation (64-wide, 213us-proven): one warp per dst node.
// out[d] = b + h[d]*dinv[d]^2 + sum_{s in N(d)} h[s]*dinv[s]*dinv[d]
// ---------------------------------------------------------------------------
__global__ void __launch_bounds__(256) k_agg64_csr(
    const float* __restrict__ h, const float* __restrict__ b,
    float* __restrict__ out, int n)
{
    int warp = (blockIdx.x * 256 + threadIdx.x) >> 5;
    int lane = threadIdx.x & 31;
    if (warp >= n) return;
    int d = warp;

    float dd = g_dinv[d];
    int start = g_ptr[d];
    int deg   = g_deg[d];

    float2 hv = *(const float2*)(h + (size_t)d * 64 + lane * 2);
    float d2 = dd * dd;
    float2 acc;
    acc.x = fmaf(hv.x, d2, b[lane * 2]);
    acc.y = fmaf(hv.y, d2, b[lane * 2 + 1]);

    for (int base = 0; base < deg; base += 32) {
        int cnt = min(32, deg - base);
        int s = 0; float w = 0.f;
        if (lane < cnt) {
            s = g_csr[start + base + lane];
            w = g_dinv[s];
        }
#pragma unroll 4
        for (int j = 0; j < cnt; j++) {
            int   sj = __shfl_sync(0xffffffffu, s, j);
            float wj = __shfl_sync(0xffffffffu, w, j);
            float coef = wj * dd;
            float2 hs = *(const float2*)(h + (size_t)sj * 64 + lane * 2);
            acc.x = fmaf(hs.x, coef, acc.x);
            acc.y = fmaf(hs.y, coef, acc.y);
        }
    }
    *(float2*)(out + (size_t)d * 64 + lane * 2) = acc;
}

// ---------------------------------------------------------------------------
// Layer 3 GEMM: relu(in[n x 64]) @ W3[64 x 7] -> h3 only
// ---------------------------------------------------------------------------
__global__ void __launch_bounds__(256) k_gemm7(
    const float* __restrict__ in, const float* __restrict__ W,
    float* __restrict__ h_out, int n)
{
    __shared__ float wsh[64 * 7];
    int tid = threadIdx.x;
    for (int i = tid; i < 448; i += 256) wsh[i] = W[i];
    __syncthreads();

    int row = blockIdx.x * blockDim.x + tid;
    if (row >= n) return;

    float acc[7];
#pragma unroll
    for (int c = 0; c < 7; c++) acc[c] = 0.f;

    const float* p = in + (size_t)row * 64;
#pragma unroll
    for (int k = 0; k < 64; k += 4) {
        float4 v = *(const float4*)(p + k);
        v.x = fmaxf(v.x, 0.f); v.y = fmaxf(v.y, 0.f);
        v.z = fmaxf(v.z, 0.f); v.w = fmaxf(v.w, 0.f);
#pragma unroll
        for (int c = 0; c < 7; c++) {
            acc[c] = fmaf(v.x, wsh[(k + 0) * 7 + c], acc[c]);
            acc[c] = fmaf(v.y, wsh[(k + 1) * 7 + c], acc[c]);
            acc[c] = fmaf(v.z, wsh[(k + 2) * 7 + c], acc[c]);
            acc[c] = fmaf(v.w, wsh[(k + 3) * 7 + c], acc[c]);
        }
    }
#pragma unroll
    for (int c = 0; c < 7; c++)
        h_out[(size_t)row * 7 + c] = acc[c];
}

// ---------------------------------------------------------------------------
// CSR pull aggregation (7-wide): one warp per dst node, lanes 0..6 hold cols.
// ---------------------------------------------------------------------------
__global__ void __launch_bounds__(256) k_agg7_csr(
    const float* __restrict__ h, const float* __restrict__ b,
    float* __restrict__ out, int n)
{
    int warp = (blockIdx.x * 256 + threadIdx.x) >> 5;
    int lane = threadIdx.x & 31;
    if (warp >= n) return;
    int d = warp;

    float dd = g_dinv[d];
    int start = g_ptr[d];
    int deg   = g_deg[d];

    float acc = 0.f;
    if (lane < 7)
        acc = fmaf(h[(size_t)d * 7 + lane], dd * dd, b[lane]);

    for (int base = 0; base < deg; base += 32) {
        int cnt = min(32, deg - base);
        int s = 0; float w = 0.f;
        if (lane < cnt) {
            s = g_csr[start + base + lane];
            w = g_dinv[s];
        }
        for (int j = 0; j < cnt; j++) {
            int   sj = __shfl_sync(0xffffffffu, s, j);
            float wj = __shfl_sync(0xffffffffu, w, j);
            if (lane < 7)
                acc = fmaf(h[(size_t)sj * 7 + lane], wj * dd, acc);
        }
    }
    if (lane < 7)
        out[(size_t)d * 7 + lane] = acc;
}

// ---------------------------------------------------------------------------
// launch
// ---------------------------------------------------------------------------
extern "C" void kernel_launch(void* const* d_in, const int* in_sizes, int n_in,
                              void* d_out, int out_size)
{
    const float* x  = (const float*)d_in[0];
    const int*   ei = (const int*)d_in[1];
    const float* W1 = (const float*)d_in[2];
    const float* b1 = (const float*)d_in[3];
    const float* W2 = (const float*)d_in[4];
    const float* b2 = (const float*)d_in[5];
    const float* W3 = (const float*)d_in[6];
    const float* b3 = (const float*)d_in[7];

    int n  = in_sizes[0] / 128;
    int nE = in_sizes[1] / 2;
    float* out = (float*)d_out;

    float *bufA, *bufB, *h3;
    cudaGetSymbolAddress((void**)&bufA, g_bufA);
    cudaGetSymbolAddress((void**)&bufB, g_bufB);
    cudaGetSymbolAddress((void**)&h3,   g_h3);

    int nb_n = (n + 255) / 256;
    int nb_e = (nE + 255) / 256;
    int nb_g = (n + 63) / 64;
    int nb_w = (int)(((long long)n * 32 + 255) / 256);

    // degree + CSR + dinv (once, reused by all 3 layers)
    k_zero_deg<<<nb_n, 256>>>(n);
    k_count_deg<<<nb_e, 256>>>(ei, nE);
    k_scanA<<<nb_n, 256>>>(n);
    k_scanC<<<nb_n, 256>>>(n);
    k_fill<<<nb_e, 256>>>(ei, nE);

    // layer 1: h1 = x@W1 -> bufA ; bufB = agg(h1) + b1
    k_gemm64<128, false><<<nb_g, 256>>>(x, W1, bufA, n);
    k_agg64_csr<<<nb_w, 256>>>(bufA, b1, bufB, n);

    // layer 2: h2 = relu(bufB)@W2 -> bufA ; bufB = agg(h2) + b2
    k_gemm64<64, true><<<nb_g, 256>>>(bufB, W2, bufA, n);
    k_agg64_csr<<<nb_w, 256>>>(bufA, b2, bufB, n);

    // layer 3: h3 = relu(bufB)@W3 ; d_out = agg(h3) + b3
    k_gemm7<<<nb_n, 256>>>(bufB, W3, h3, n);
    k_agg7_csr<<<nb_w, 256>>>(h3, b3, out, n);
}